// round 14
// baseline (speedup 1.0000x reference)
#include <cuda_runtime.h>
#include <cuda_fp16.h>
#include <cstdint>
#include <math.h>

#define B_   8
#define C_   512
#define N_   2048
#define GROUPS_ 32
#define CPG  16
#define EPSF 1e-6f

#define NC_ ((size_t)N_ * C_)      // 1048576
#define NN_ ((size_t)N_ * N_)      // 4194304

// ---------------- scratch ----------------
__device__ __half g_hTh [B_ * N_ * C_];          // groupnorm out, [b][n][c] half
__device__ __half g_qTh [B_ * N_ * C_];          // [b][n][c]
__device__ __half g_kTh [B_ * N_ * C_];          // [b][n][c]
__device__ __half g_vh  [B_ * C_ * N_];          // [b][c][n]
__device__ __half g_ph  [(size_t)B_ * N_ * N_];  // logits -> probs, half, in-place
__device__ __half g_h2Th[B_ * N_ * C_];          // [b][i][c]
__device__ __half g_wh  [4 * C_ * C_];           // wq,wk,wv,wp as half

// ---------------- helpers ----------------
__device__ __forceinline__ uint32_t smem_u32(const void* p) {
    uint32_t a;
    asm("{ .reg .u64 t; cvta.to.shared.u64 t, %1; cvt.u32.u64 %0, t; }" : "=r"(a) : "l"(p));
    return a;
}
__device__ __forceinline__ void cp_async16(uint32_t dst, const void* src) {
    asm volatile("cp.async.cg.shared.global [%0], [%1], 16;" :: "r"(dst), "l"(src));
}
#define CP_COMMIT() asm volatile("cp.async.commit_group;" ::: "memory")
#define CP_WAIT0()  asm volatile("cp.async.wait_group 0;" ::: "memory")

__device__ __forceinline__ void mma_f16(float* c, const uint32_t* a, const uint32_t* b) {
    asm volatile("mma.sync.aligned.m16n8k16.row.col.f32.f16.f16.f32 "
                 "{%0,%1,%2,%3}, {%4,%5,%6,%7}, {%8,%9}, {%0,%1,%2,%3};"
                 : "+f"(c[0]), "+f"(c[1]), "+f"(c[2]), "+f"(c[3])
                 : "r"(a[0]), "r"(a[1]), "r"(a[2]), "r"(a[3]), "r"(b[0]), "r"(b[1]));
}
__device__ __forceinline__ void ldm_x4(uint32_t& r0, uint32_t& r1, uint32_t& r2, uint32_t& r3,
                                       uint32_t addr) {
    asm volatile("ldmatrix.sync.aligned.m8n8.x4.shared.b16 {%0,%1,%2,%3}, [%4];"
                 : "=r"(r0), "=r"(r1), "=r"(r2), "=r"(r3) : "r"(addr));
}

// ---------------- weight fp32 -> fp16 ----------------
__global__ __launch_bounds__(256) void cvt_w_kernel(const float* __restrict__ wq,
                                                    const float* __restrict__ wk,
                                                    const float* __restrict__ wv,
                                                    const float* __restrict__ wp) {
    const float* src = (blockIdx.y == 0) ? wq : (blockIdx.y == 1) ? wk
                       : (blockIdx.y == 2) ? wv : wp;
    __half* dst = g_wh + (size_t)blockIdx.y * C_ * C_;
    int i = (blockIdx.x * 256 + threadIdx.x) * 4;
    float4 v = *(const float4*)(src + i);
    __half2 h0 = __floats2half2_rn(v.x, v.y);
    __half2 h1 = __floats2half2_rn(v.z, v.w);
    *(uint2*)(dst + i) = make_uint2(*(uint32_t*)&h0, *(uint32_t*)&h1);
}

// ---------------- GroupNorm (writes transposed half hT[b][n][c]) ----------------
__global__ __launch_bounds__(256) void groupnorm_kernel(const float* __restrict__ x,
                                                        const float* __restrict__ scale,
                                                        const float* __restrict__ bias) {
    int bg = blockIdx.x;
    int b = bg / GROUPS_, g = bg % GROUPS_;
    const float* xp  = x + ((size_t)b * C_ + (size_t)g * CPG) * N_;
    __half*      hpT = g_hTh + (size_t)b * NC_;
    int tid = threadIdx.x;
    const int total = CPG * N_;  // 32768

    float s = 0.f, ss = 0.f;
    for (int i = tid; i < total; i += 256) {
        float v = xp[i];
        s += v; ss += v * v;
    }
    __shared__ float rs[256], rq[256];
    rs[tid] = s; rq[tid] = ss;
    __syncthreads();
    for (int off = 128; off > 0; off >>= 1) {
        if (tid < off) { rs[tid] += rs[tid + off]; rq[tid] += rq[tid + off]; }
        __syncthreads();
    }
    float mean = rs[0] / (float)total;
    float var  = rq[0] / (float)total - mean * mean;
    float rinv = rsqrtf(var + EPSF);

    __shared__ float tile[128][17];
    for (int n0 = 0; n0 < N_; n0 += 128) {
        __syncthreads();
        int nl = tid & 127;
        int ch = tid >> 7;
        #pragma unroll
        for (int cp = 0; cp < 8; cp++) {
            int c = cp * 2 + ch;
            int cabs = g * CPG + c;
            tile[nl][c] = (xp[(size_t)c * N_ + n0 + nl] - mean) * rinv * scale[cabs] + bias[cabs];
        }
        __syncthreads();
        int row = tid >> 1;
        int half = (tid & 1) * 8;
        __half* dst = hpT + (size_t)(n0 + row) * C_ + g * CPG + half;
        __half2 h0 = __floats2half2_rn(tile[row][half + 0], tile[row][half + 1]);
        __half2 h1 = __floats2half2_rn(tile[row][half + 2], tile[row][half + 3]);
        __half2 h2 = __floats2half2_rn(tile[row][half + 4], tile[row][half + 5]);
        __half2 h3 = __floats2half2_rn(tile[row][half + 6], tile[row][half + 7]);
        *(uint4*)dst = make_uint4(*(uint32_t*)&h0, *(uint32_t*)&h1,
                                  *(uint32_t*)&h2, *(uint32_t*)&h3);
    }
}

// ---------------- fp16 mma.sync GEMM (512 thr, 4x4 warps, 32x32 warp tile) ----------------
// D[m][n] = sum_k A[m][k] * B[n][k], both K-major half.
#define MODE_SCALE 2   // * scale, D half            (QK logits)
#define MODE_NONE  3   // D half                     (PV)
#define MODE_OUT   4   // + bias[row] + resid, float (proj)
#define MODE_QKV   5   // flat grid: seg0/1 colbias q/k; seg2 rowbias v

#define BKH    64
#define PADH   72
#define STAGEH (128 * PADH)
#define GSMEM  (3 * 2 * STAGEH * 2)   // 110592 bytes
#define NTHR   512

template <int MODE, int NCK>
__global__ __launch_bounds__(NTHR, 1)
void gemm_kernel(const __half* __restrict__ A, const __half* __restrict__ Bm,
                 void* __restrict__ Dv,
                 const float* __restrict__ bias, const float* __restrict__ resid,
                 const __half* __restrict__ Bm2, const float* __restrict__ bias2,
                 void* __restrict__ Dv2,
                 const __half* __restrict__ Bm3, const float* __restrict__ bias3,
                 void* __restrict__ Dv3,
                 int lda, int ldb, int ldd,
                 size_t a_bs, size_t b_bs, size_t d_bs, size_t r_bs) {
    extern __shared__ __half smem[];

    int tid = threadIdx.x, lane = tid & 31, wid = tid >> 5;
    int warp_m = wid & 3;     // 4 warps over M (32 rows each)
    int warp_n = wid >> 2;    // 4 warps over N (32 cols each)

    int b, m0, n0, seg = 0;
    const __half* Aptr = A;
    const __half* Bptr = Bm;
    const float*  bsel = bias;
    void*         Dsel = Dv;
    int lddv = ldd;
    if (MODE == MODE_QKV) {
        int id = blockIdx.x;
        seg = id >> 9;                  // 0:q 1:k 2:v
        int r = id & 511;
        int bx, by;
        if (seg < 2) { bx = r & 3;  by = (r >> 2) & 15; }
        else         { bx = r & 15; by = (r >> 4) & 3;  }
        b = r >> 6;                     // 64 tiles per batch in every segment
        m0 = by * 128; n0 = bx * 128;
        if (seg == 0) { /* defaults */ }
        else if (seg == 1) { Bptr = Bm2; bsel = bias2; Dsel = Dv2; }
        else { Aptr = Bm3; Bptr = A; bsel = bias3; Dsel = Dv3; lddv = N_; }
    } else {
        b = blockIdx.z;
        m0 = blockIdx.y * 128; n0 = blockIdx.x * 128;
    }

    const __half* Ab;
    const __half* Bb;
    if (MODE == MODE_QKV) {
        if (seg < 2) { Ab = Aptr + (size_t)b * NC_; Bb = Bptr; }
        else         { Ab = Aptr;                   Bb = Bptr + (size_t)b * NC_; }
    } else {
        Ab = Aptr + (size_t)b * a_bs;
        Bb = Bptr + (size_t)b * b_bs;
    }

    uint32_t sbase = smem_u32(smem);

    auto load_stage = [&](int stage, int k0) {
        uint32_t sa = sbase + (uint32_t)stage * (2u * STAGEH * 2u);
        uint32_t sb = sa + STAGEH * 2u;
        #pragma unroll
        for (int t = 0; t < 2; t++) {
            int idx = t * NTHR + tid;           // 1024 16B-vectors per operand
            int r = idx >> 3, c = idx & 7;
            uint32_t off = (uint32_t)(r * PADH + c * 8) * 2u;
            cp_async16(sa + off, Ab + (size_t)(m0 + r) * lda + k0 + c * 8);
            cp_async16(sb + off, Bb + (size_t)(n0 + r) * ldb + k0 + c * 8);
        }
    };

    int l7  = lane & 7;
    int l8  = (lane >> 3) & 1;
    int l16 = lane >> 4;
    int aoff = (warp_m * 32 + l7 + l8 * 8) * PADH + l16 * 8;
    int boff = (warp_n * 32 + l7 + l16 * 8) * PADH + l8 * 8;

    auto ldfragA = [&](uint32_t sa, int kbase, uint32_t fa[2][4]) {
        #pragma unroll
        for (int mt = 0; mt < 2; mt++) {
            uint32_t addr = sa + (uint32_t)(aoff + mt * 16 * PADH + kbase) * 2u;
            ldm_x4(fa[mt][0], fa[mt][1], fa[mt][2], fa[mt][3], addr);
        }
    };
    auto ldfragB = [&](uint32_t sb, int kbase, uint32_t fb[4][2]) {
        #pragma unroll
        for (int pp = 0; pp < 2; pp++) {
            uint32_t addr = sb + (uint32_t)(boff + pp * 16 * PADH + kbase) * 2u;
            ldm_x4(fb[2 * pp][0], fb[2 * pp][1], fb[2 * pp + 1][0], fb[2 * pp + 1][1], addr);
        }
    };

    float acc[2][4][4];
    #pragma unroll
    for (int i = 0; i < 2; i++)
        #pragma unroll
        for (int j = 0; j < 4; j++)
            #pragma unroll
            for (int t = 0; t < 4; t++) acc[i][j][t] = 0.f;

    uint32_t fA[2][2][4];   // double-buffered A fragments
    uint32_t fB[2][4][2];   // double-buffered B fragments

    load_stage(0, 0);
    CP_COMMIT();
    CP_WAIT0();
    __syncthreads();
    load_stage(1, BKH);
    CP_COMMIT();
    ldfragA(sbase, 0, fA[0]);
    ldfragB(sbase + STAGEH * 2u, 0, fB[0]);

    int stage = 0;
    #pragma unroll 1
    for (int ck = 0; ck < NCK; ck++) {
        CP_WAIT0();
        __syncthreads();

        int lst = stage + 2; if (lst >= 3) lst -= 3;
        if (ck + 2 < NCK) load_stage(lst, (ck + 2) * BKH);
        CP_COMMIT();

        uint32_t sa = sbase + (uint32_t)stage * (2u * STAGEH * 2u);
        uint32_t sb = sa + STAGEH * 2u;
        int nst = stage + 1; if (nst >= 3) nst -= 3;
        uint32_t xsa = sbase + (uint32_t)nst * (2u * STAGEH * 2u);
        uint32_t xsb = xsa + STAGEH * 2u;

        #pragma unroll
        for (int kk = 0; kk < 4; kk++) {
            int cur = kk & 1, nxt = cur ^ 1;
            if (kk < 3) {
                ldfragA(sa, (kk + 1) * 16, fA[nxt]);
                ldfragB(sb, (kk + 1) * 16, fB[nxt]);
            } else {      // cross-chunk prefetch (stage ck+1 already resident)
                ldfragA(xsa, 0, fA[nxt]);
                ldfragB(xsb, 0, fB[nxt]);
            }
            #pragma unroll
            for (int mt = 0; mt < 2; mt++)
                #pragma unroll
                for (int nt = 0; nt < 4; nt++)
                    mma_f16(acc[mt][nt], fA[cur][mt], fB[cur][nt]);
        }
        stage = nst;
    }

    // epilogue
    constexpr bool HALF_OUT = (MODE != MODE_OUT);
    int rbase = m0 + warp_m * 32 + (lane >> 2);
    int cbase = n0 + warp_n * 32 + (lane & 3) * 2;
    bool rowbias = (MODE == MODE_OUT) || (MODE == MODE_QKV && seg == 2);
    bool colbias = (MODE == MODE_QKV && seg < 2);
    #pragma unroll
    for (int mt = 0; mt < 2; mt++) {
        int r0 = rbase + mt * 16;
        int r1 = r0 + 8;
        float rb0 = 0.f, rb1 = 0.f;
        if (rowbias) { rb0 = bsel[r0]; rb1 = bsel[r1]; }
        #pragma unroll
        for (int nt = 0; nt < 4; nt++) {
            int cc = cbase + nt * 8;
            float e0 = acc[mt][nt][0], e1 = acc[mt][nt][1];
            float e2 = acc[mt][nt][2], e3 = acc[mt][nt][3];
            if (colbias) {
                float b0 = bsel[cc], b1 = bsel[cc + 1];
                e0 += b0; e1 += b1; e2 += b0; e3 += b1;
            } else if (MODE == MODE_SCALE) {
                const float scl = 0.044194173824159216f;
                e0 *= scl; e1 *= scl; e2 *= scl; e3 *= scl;
            } else if (rowbias) {
                e0 += rb0; e1 += rb0; e2 += rb1; e3 += rb1;
            }
            if (MODE == MODE_OUT) {
                const float* rp0 = resid + (size_t)b * r_bs + (size_t)r0 * lddv + cc;
                const float* rp1 = resid + (size_t)b * r_bs + (size_t)r1 * lddv + cc;
                e0 += rp0[0]; e1 += rp0[1];
                e2 += rp1[0]; e3 += rp1[1];
            }
            if (HALF_OUT) {
                __half* Dh = (__half*)Dsel + (size_t)b * ((MODE == MODE_QKV) ? NC_ : d_bs);
                __half2 h0 = __floats2half2_rn(e0, e1);
                __half2 h1 = __floats2half2_rn(e2, e3);
                *(__half2*)(Dh + (size_t)r0 * lddv + cc) = h0;
                *(__half2*)(Dh + (size_t)r1 * lddv + cc) = h1;
            } else {
                float* Df = (float*)Dsel + (size_t)b * d_bs;
                float2 o0; o0.x = e0; o0.y = e1;
                float2 o1; o1.x = e2; o1.y = e3;
                *(float2*)(Df + (size_t)r0 * lddv + cc) = o0;
                *(float2*)(Df + (size_t)r1 * lddv + cc) = o1;
            }
        }
    }
}

// ---------------- row softmax: half logits -> half probs (in place) ----------------
__global__ __launch_bounds__(256) void softmax_kernel() {
    size_t row = blockIdx.x;
    uint2* p4 = (uint2*)(g_ph + row * N_);
    int tid = threadIdx.x;

    uint2 ua = p4[tid];
    uint2 ub = p4[tid + 256];
    __half2 a0 = *(__half2*)&ua.x, a1 = *(__half2*)&ua.y;
    __half2 b0 = *(__half2*)&ub.x, b1 = *(__half2*)&ub.y;
    float2 fa0 = __half22float2(a0), fa1 = __half22float2(a1);
    float2 fb0 = __half22float2(b0), fb1 = __half22float2(b1);

    float mx = fmaxf(fmaxf(fmaxf(fa0.x, fa0.y), fmaxf(fa1.x, fa1.y)),
                     fmaxf(fmaxf(fb0.x, fb0.y), fmaxf(fb1.x, fb1.y)));

    __shared__ float red[256];
    red[tid] = mx; __syncthreads();
    for (int off = 128; off > 0; off >>= 1) {
        if (tid < off) red[tid] = fmaxf(red[tid], red[tid + off]);
        __syncthreads();
    }
    mx = red[0]; __syncthreads();

    fa0.x = __expf(fa0.x - mx); fa0.y = __expf(fa0.y - mx);
    fa1.x = __expf(fa1.x - mx); fa1.y = __expf(fa1.y - mx);
    fb0.x = __expf(fb0.x - mx); fb0.y = __expf(fb0.y - mx);
    fb1.x = __expf(fb1.x - mx); fb1.y = __expf(fb1.y - mx);
    float s = (fa0.x + fa0.y + fa1.x + fa1.y) + (fb0.x + fb0.y + fb1.x + fb1.y);

    red[tid] = s; __syncthreads();
    for (int off = 128; off > 0; off >>= 1) {
        if (tid < off) red[tid] += red[tid + off];
        __syncthreads();
    }
    float rinv = 1.f / red[0];

    __half2 oa0 = __floats2half2_rn(fa0.x * rinv, fa0.y * rinv);
    __half2 oa1 = __floats2half2_rn(fa1.x * rinv, fa1.y * rinv);
    __half2 ob0 = __floats2half2_rn(fb0.x * rinv, fb0.y * rinv);
    __half2 ob1 = __floats2half2_rn(fb1.x * rinv, fb1.y * rinv);
    p4[tid]       = make_uint2(*(uint32_t*)&oa0, *(uint32_t*)&oa1);
    p4[tid + 256] = make_uint2(*(uint32_t*)&ob0, *(uint32_t*)&ob1);
}

// ---------------- launch ----------------
extern "C" void kernel_launch(void* const* d_in, const int* in_sizes, int n_in,
                              void* d_out, int out_size) {
    const float* x  = (const float*)d_in[0];
    const float* gs = (const float*)d_in[1];
    const float* gb = (const float*)d_in[2];
    const float* wq = (const float*)d_in[3];
    const float* bq = (const float*)d_in[4];
    const float* wk = (const float*)d_in[5];
    const float* bk = (const float*)d_in[6];
    const float* wv = (const float*)d_in[7];
    const float* bv = (const float*)d_in[8];
    const float* wp = (const float*)d_in[9];
    const float* bp = (const float*)d_in[10];
    float* out = (float*)d_out;

    cudaFuncSetAttribute(gemm_kernel<MODE_QKV, 8>,    cudaFuncAttributeMaxDynamicSharedMemorySize, GSMEM);
    cudaFuncSetAttribute(gemm_kernel<MODE_SCALE, 8>,  cudaFuncAttributeMaxDynamicSharedMemorySize, GSMEM);
    cudaFuncSetAttribute(gemm_kernel<MODE_NONE, 32>,  cudaFuncAttributeMaxDynamicSharedMemorySize, GSMEM);
    cudaFuncSetAttribute(gemm_kernel<MODE_OUT, 8>,    cudaFuncAttributeMaxDynamicSharedMemorySize, GSMEM);

    __half* hTh  = nullptr; cudaGetSymbolAddress((void**)&hTh,  g_hTh);
    __half* qTh  = nullptr; cudaGetSymbolAddress((void**)&qTh,  g_qTh);
    __half* kTh  = nullptr; cudaGetSymbolAddress((void**)&kTh,  g_kTh);
    __half* vh   = nullptr; cudaGetSymbolAddress((void**)&vh,   g_vh);
    __half* ph   = nullptr; cudaGetSymbolAddress((void**)&ph,   g_ph);
    __half* h2Th = nullptr; cudaGetSymbolAddress((void**)&h2Th, g_h2Th);
    __half* wh   = nullptr; cudaGetSymbolAddress((void**)&wh,   g_wh);
    __half* wqh = wh;
    __half* wkh = wh + (size_t)C_ * C_;
    __half* wvh = wh + 2 * (size_t)C_ * C_;
    __half* wph = wh + 3 * (size_t)C_ * C_;

    cvt_w_kernel<<<dim3(C_ * C_ / 1024, 4), 256>>>(wq, wk, wv, wp);
    groupnorm_kernel<<<B_ * GROUPS_, 256>>>(x, gs, gb);

    // merged QKV: 1536 blocks. seg0: qT = hT*wq^T + bq (col); seg1: kT; seg2: v = wv*hT^T + bv (row)
    gemm_kernel<MODE_QKV, 8><<<1536, NTHR, GSMEM>>>(
        hTh, wqh, qTh, bq, nullptr, wkh, bk, kTh, wvh, bv, vh,
        C_, C_, C_, NC_, 0, NC_, 0);

    // logits[i][j] = scale * sum_c qT[i][c] kT[j][c]  M=2048 N=2048 K=512 -> half
    gemm_kernel<MODE_SCALE, 8><<<dim3(16, 16, B_), NTHR, GSMEM>>>(
        qTh, kTh, ph, nullptr, nullptr, nullptr, nullptr, nullptr, nullptr, nullptr, nullptr,
        C_, C_, N_, NC_, NC_, NN_, 0);

    softmax_kernel<<<B_ * N_, 256>>>();

    // h2T[i][c] = sum_j P[i][j] v[c][j]               M=2048 N=512 K=2048
    gemm_kernel<MODE_NONE, 32><<<dim3(4, 16, B_), NTHR, GSMEM>>>(
        ph, vh, h2Th, nullptr, nullptr, nullptr, nullptr, nullptr, nullptr, nullptr, nullptr,
        N_, N_, C_, NN_, NC_, NC_, 0);

    // out[o][n] = x + bp[o] + sum_c wp[o][c] h2T[n][c]  M=512 N=2048 K=512
    gemm_kernel<MODE_OUT, 8><<<dim3(16, 4, B_), NTHR, GSMEM>>>(
        wph, h2Th, out, bp, x, nullptr, nullptr, nullptr, nullptr, nullptr, nullptr,
        C_, C_, N_, 0, NC_, NC_, NC_);
}

// round 15
// speedup vs baseline: 1.2280x; 1.2280x over previous
#include <cuda_runtime.h>
#include <cuda_fp16.h>
#include <cstdint>
#include <math.h>

#define B_   8
#define C_   512
#define N_   2048
#define GROUPS_ 32
#define CPG  16
#define EPSF 1e-6f

#define NC_ ((size_t)N_ * C_)      // 1048576
#define NN_ ((size_t)N_ * N_)      // 4194304

// ---------------- scratch ----------------
__device__ __half g_hTh [B_ * N_ * C_];          // groupnorm out, [b][n][c] half
__device__ __half g_qTh [B_ * N_ * C_];          // [b][n][c]
__device__ __half g_kTh [B_ * N_ * C_];          // [b][n][c]
__device__ __half g_vh  [B_ * C_ * N_];          // [b][c][n]
__device__ __half g_ph  [(size_t)B_ * N_ * N_];  // logits -> probs, half, in-place
__device__ __half g_h2Th[B_ * N_ * C_];          // [b][i][c]
__device__ __half g_wh  [4 * C_ * C_];           // wq,wk,wv,wp as half

// ---------------- helpers ----------------
__device__ __forceinline__ uint32_t smem_u32(const void* p) {
    uint32_t a;
    asm("{ .reg .u64 t; cvta.to.shared.u64 t, %1; cvt.u32.u64 %0, t; }" : "=r"(a) : "l"(p));
    return a;
}
__device__ __forceinline__ void cp_async16(uint32_t dst, const void* src) {
    asm volatile("cp.async.cg.shared.global [%0], [%1], 16;" :: "r"(dst), "l"(src));
}
#define CP_COMMIT() asm volatile("cp.async.commit_group;" ::: "memory")
#define CP_WAIT0()  asm volatile("cp.async.wait_group 0;" ::: "memory")

__device__ __forceinline__ void mma_f16(float* c, const uint32_t* a, const uint32_t* b) {
    asm volatile("mma.sync.aligned.m16n8k16.row.col.f32.f16.f16.f32 "
                 "{%0,%1,%2,%3}, {%4,%5,%6,%7}, {%8,%9}, {%0,%1,%2,%3};"
                 : "+f"(c[0]), "+f"(c[1]), "+f"(c[2]), "+f"(c[3])
                 : "r"(a[0]), "r"(a[1]), "r"(a[2]), "r"(a[3]), "r"(b[0]), "r"(b[1]));
}
__device__ __forceinline__ void ldm_x4(uint32_t& r0, uint32_t& r1, uint32_t& r2, uint32_t& r3,
                                       uint32_t addr) {
    asm volatile("ldmatrix.sync.aligned.m8n8.x4.shared.b16 {%0,%1,%2,%3}, [%4];"
                 : "=r"(r0), "=r"(r1), "=r"(r2), "=r"(r3) : "r"(addr));
}

// ---------------- weight fp32 -> fp16 ----------------
__global__ __launch_bounds__(256) void cvt_w_kernel(const float* __restrict__ wq,
                                                    const float* __restrict__ wk,
                                                    const float* __restrict__ wv,
                                                    const float* __restrict__ wp) {
    const float* src = (blockIdx.y == 0) ? wq : (blockIdx.y == 1) ? wk
                       : (blockIdx.y == 2) ? wv : wp;
    __half* dst = g_wh + (size_t)blockIdx.y * C_ * C_;
    int i = (blockIdx.x * 256 + threadIdx.x) * 4;
    float4 v = *(const float4*)(src + i);
    __half2 h0 = __floats2half2_rn(v.x, v.y);
    __half2 h1 = __floats2half2_rn(v.z, v.w);
    *(uint2*)(dst + i) = make_uint2(*(uint32_t*)&h0, *(uint32_t*)&h1);
}

// ---------------- GroupNorm (writes transposed half hT[b][n][c]) ----------------
__global__ __launch_bounds__(256) void groupnorm_kernel(const float* __restrict__ x,
                                                        const float* __restrict__ scale,
                                                        const float* __restrict__ bias) {
    int bg = blockIdx.x;
    int b = bg / GROUPS_, g = bg % GROUPS_;
    const float* xp  = x + ((size_t)b * C_ + (size_t)g * CPG) * N_;
    __half*      hpT = g_hTh + (size_t)b * NC_;
    int tid = threadIdx.x;
    const int total = CPG * N_;  // 32768

    float s = 0.f, ss = 0.f;
    for (int i = tid; i < total; i += 256) {
        float v = xp[i];
        s += v; ss += v * v;
    }
    __shared__ float rs[256], rq[256];
    rs[tid] = s; rq[tid] = ss;
    __syncthreads();
    for (int off = 128; off > 0; off >>= 1) {
        if (tid < off) { rs[tid] += rs[tid + off]; rq[tid] += rq[tid + off]; }
        __syncthreads();
    }
    float mean = rs[0] / (float)total;
    float var  = rq[0] / (float)total - mean * mean;
    float rinv = rsqrtf(var + EPSF);

    __shared__ float tile[128][17];
    for (int n0 = 0; n0 < N_; n0 += 128) {
        __syncthreads();
        int nl = tid & 127;
        int ch = tid >> 7;
        #pragma unroll
        for (int cp = 0; cp < 8; cp++) {
            int c = cp * 2 + ch;
            int cabs = g * CPG + c;
            tile[nl][c] = (xp[(size_t)c * N_ + n0 + nl] - mean) * rinv * scale[cabs] + bias[cabs];
        }
        __syncthreads();
        int row = tid >> 1;
        int half = (tid & 1) * 8;
        __half* dst = hpT + (size_t)(n0 + row) * C_ + g * CPG + half;
        __half2 h0 = __floats2half2_rn(tile[row][half + 0], tile[row][half + 1]);
        __half2 h1 = __floats2half2_rn(tile[row][half + 2], tile[row][half + 3]);
        __half2 h2 = __floats2half2_rn(tile[row][half + 4], tile[row][half + 5]);
        __half2 h3 = __floats2half2_rn(tile[row][half + 6], tile[row][half + 7]);
        *(uint4*)dst = make_uint4(*(uint32_t*)&h0, *(uint32_t*)&h1,
                                  *(uint32_t*)&h2, *(uint32_t*)&h3);
    }
}

// ---------------- fp16 mma.sync GEMM (champion mainloop: 256 thr, 32x64 warp tile,
//                  ldmatrix, BOTH fragment paths double-buffered) ----------------
// D[m][n] = sum_k A[m][k] * B[n][k], both K-major half.
#define MODE_SCALE 2   // * scale, D half            (QK logits)
#define MODE_NONE  3   // D half                     (PV)
#define MODE_OUT   4   // + bias[row] + resid, float (proj)
#define MODE_QKV   5   // flat grid: seg0/1 colbias q/k; seg2 rowbias v

#define BKH    64
#define PADH   72
#define STAGEH (128 * PADH)
#define GSMEM  (3 * 2 * STAGEH * 2)   // 110592 bytes

template <int MODE, int NCK>
__global__ __launch_bounds__(256, 2)
void gemm_kernel(const __half* __restrict__ A, const __half* __restrict__ Bm,
                 void* __restrict__ Dv,
                 const float* __restrict__ bias, const float* __restrict__ resid,
                 const __half* __restrict__ Bm2, const float* __restrict__ bias2,
                 void* __restrict__ Dv2,
                 const __half* __restrict__ Bm3, const float* __restrict__ bias3,
                 void* __restrict__ Dv3,
                 int lda, int ldb, int ldd,
                 size_t a_bs, size_t b_bs, size_t d_bs, size_t r_bs) {
    extern __shared__ __half smem[];

    int tid = threadIdx.x, lane = tid & 31, wid = tid >> 5;
    int warp_m = wid & 3;     // 4 warps over M (32 rows)
    int warp_n = wid >> 2;    // 2 warps over N (64 cols)

    int b, m0, n0, seg = 0;
    const __half* Aptr = A;
    const __half* Bptr = Bm;
    const float*  bsel = bias;
    void*         Dsel = Dv;
    int lddv = ldd;
    if (MODE == MODE_QKV) {
        int id = blockIdx.x;
        seg = id >> 9;                  // 0:q 1:k 2:v
        int r = id & 511;
        int bx, by;
        if (seg < 2) { bx = r & 3;  by = (r >> 2) & 15; }
        else         { bx = r & 15; by = (r >> 4) & 3;  }
        b = r >> 6;                     // 64 tiles per batch in every segment
        m0 = by * 128; n0 = bx * 128;
        if (seg == 0) { /* defaults */ }
        else if (seg == 1) { Bptr = Bm2; bsel = bias2; Dsel = Dv2; }
        else { Aptr = Bm3; Bptr = A; bsel = bias3; Dsel = Dv3; lddv = N_; }
    } else {
        b = blockIdx.z;
        m0 = blockIdx.y * 128; n0 = blockIdx.x * 128;
    }

    const __half* Ab;
    const __half* Bb;
    if (MODE == MODE_QKV) {
        if (seg < 2) { Ab = Aptr + (size_t)b * NC_; Bb = Bptr; }
        else         { Ab = Aptr;                   Bb = Bptr + (size_t)b * NC_; }
    } else {
        Ab = Aptr + (size_t)b * a_bs;
        Bb = Bptr + (size_t)b * b_bs;
    }

    uint32_t sbase = smem_u32(smem);

    auto load_stage = [&](int stage, int k0) {
        uint32_t sa = sbase + (uint32_t)stage * (2u * STAGEH * 2u);
        uint32_t sb = sa + STAGEH * 2u;
        #pragma unroll
        for (int t = 0; t < 4; t++) {
            int idx = t * 256 + tid;
            int r = idx >> 3, c = idx & 7;
            uint32_t off = (uint32_t)(r * PADH + c * 8) * 2u;
            cp_async16(sa + off, Ab + (size_t)(m0 + r) * lda + k0 + c * 8);
            cp_async16(sb + off, Bb + (size_t)(n0 + r) * ldb + k0 + c * 8);
        }
    };

    int l7  = lane & 7;
    int l8  = (lane >> 3) & 1;
    int l16 = lane >> 4;
    int aoff = (warp_m * 32 + l7 + l8 * 8) * PADH + l16 * 8;
    int boff = (warp_n * 64 + l7 + l16 * 8) * PADH + l8 * 8;

    auto ldfragA = [&](uint32_t sa, int kbase, uint32_t fa[2][4]) {
        #pragma unroll
        for (int mt = 0; mt < 2; mt++) {
            uint32_t addr = sa + (uint32_t)(aoff + mt * 16 * PADH + kbase) * 2u;
            ldm_x4(fa[mt][0], fa[mt][1], fa[mt][2], fa[mt][3], addr);
        }
    };
    auto ldfragB = [&](uint32_t sb, int kbase, uint32_t fb[8][2]) {
        #pragma unroll
        for (int pp = 0; pp < 4; pp++) {
            uint32_t addr = sb + (uint32_t)(boff + pp * 16 * PADH + kbase) * 2u;
            ldm_x4(fb[2 * pp][0], fb[2 * pp][1], fb[2 * pp + 1][0], fb[2 * pp + 1][1], addr);
        }
    };

    float acc[2][8][4];
    #pragma unroll
    for (int i = 0; i < 2; i++)
        #pragma unroll
        for (int j = 0; j < 8; j++)
            #pragma unroll
            for (int t = 0; t < 4; t++) acc[i][j][t] = 0.f;

    uint32_t fA[2][2][4];   // double-buffered A fragments
    uint32_t fB[2][8][2];   // double-buffered B fragments

    load_stage(0, 0);
    CP_COMMIT();
    CP_WAIT0();
    __syncthreads();
    load_stage(1, BKH);
    CP_COMMIT();
    ldfragA(sbase, 0, fA[0]);
    ldfragB(sbase + STAGEH * 2u, 0, fB[0]);

    int stage = 0;
    #pragma unroll 1
    for (int ck = 0; ck < NCK; ck++) {
        CP_WAIT0();
        __syncthreads();

        int lst = stage + 2; if (lst >= 3) lst -= 3;
        if (ck + 2 < NCK) load_stage(lst, (ck + 2) * BKH);
        CP_COMMIT();

        uint32_t sa = sbase + (uint32_t)stage * (2u * STAGEH * 2u);
        uint32_t sb = sa + STAGEH * 2u;
        int nst = stage + 1; if (nst >= 3) nst -= 3;
        uint32_t xsa = sbase + (uint32_t)nst * (2u * STAGEH * 2u);
        uint32_t xsb = xsa + STAGEH * 2u;

        #pragma unroll
        for (int kk = 0; kk < 4; kk++) {
            int cur = kk & 1, nxt = cur ^ 1;
            if (kk < 3) {
                ldfragA(sa, (kk + 1) * 16, fA[nxt]);
                ldfragB(sb, (kk + 1) * 16, fB[nxt]);
            } else {      // cross-chunk prefetch (stage ck+1 already resident)
                ldfragA(xsa, 0, fA[nxt]);
                ldfragB(xsb, 0, fB[nxt]);
            }
            #pragma unroll
            for (int mt = 0; mt < 2; mt++)
                #pragma unroll
                for (int nt = 0; nt < 8; nt++)
                    mma_f16(acc[mt][nt], fA[cur][mt], fB[cur][nt]);
        }
        stage = nst;
    }

    // epilogue
    constexpr bool HALF_OUT = (MODE != MODE_OUT);
    int rbase = m0 + warp_m * 32 + (lane >> 2);
    int cbase = n0 + warp_n * 64 + (lane & 3) * 2;
    bool rowbias = (MODE == MODE_OUT) || (MODE == MODE_QKV && seg == 2);
    bool colbias = (MODE == MODE_QKV && seg < 2);
    #pragma unroll
    for (int mt = 0; mt < 2; mt++) {
        int r0 = rbase + mt * 16;
        int r1 = r0 + 8;
        float rb0 = 0.f, rb1 = 0.f;
        if (rowbias) { rb0 = bsel[r0]; rb1 = bsel[r1]; }
        #pragma unroll
        for (int nt = 0; nt < 8; nt++) {
            int cc = cbase + nt * 8;
            float e0 = acc[mt][nt][0], e1 = acc[mt][nt][1];
            float e2 = acc[mt][nt][2], e3 = acc[mt][nt][3];
            if (colbias) {
                float b0 = bsel[cc], b1 = bsel[cc + 1];
                e0 += b0; e1 += b1; e2 += b0; e3 += b1;
            } else if (MODE == MODE_SCALE) {
                const float scl = 0.044194173824159216f;
                e0 *= scl; e1 *= scl; e2 *= scl; e3 *= scl;
            } else if (rowbias) {
                e0 += rb0; e1 += rb0; e2 += rb1; e3 += rb1;
            }
            if (MODE == MODE_OUT) {
                const float* rp0 = resid + (size_t)b * r_bs + (size_t)r0 * lddv + cc;
                const float* rp1 = resid + (size_t)b * r_bs + (size_t)r1 * lddv + cc;
                e0 += rp0[0]; e1 += rp0[1];
                e2 += rp1[0]; e3 += rp1[1];
            }
            if (HALF_OUT) {
                __half* Dh = (__half*)Dsel + (size_t)b * ((MODE == MODE_QKV) ? NC_ : d_bs);
                __half2 h0 = __floats2half2_rn(e0, e1);
                __half2 h1 = __floats2half2_rn(e2, e3);
                *(__half2*)(Dh + (size_t)r0 * lddv + cc) = h0;
                *(__half2*)(Dh + (size_t)r1 * lddv + cc) = h1;
            } else {
                float* Df = (float*)Dsel + (size_t)b * d_bs;
                float2 o0; o0.x = e0; o0.y = e1;
                float2 o1; o1.x = e2; o1.y = e3;
                *(float2*)(Df + (size_t)r0 * lddv + cc) = o0;
                *(float2*)(Df + (size_t)r1 * lddv + cc) = o1;
            }
        }
    }
}

// ---------------- row softmax: half logits -> half probs (in place) ----------------
__global__ __launch_bounds__(256) void softmax_kernel() {
    size_t row = blockIdx.x;
    uint2* p4 = (uint2*)(g_ph + row * N_);
    int tid = threadIdx.x;

    uint2 ua = p4[tid];
    uint2 ub = p4[tid + 256];
    __half2 a0 = *(__half2*)&ua.x, a1 = *(__half2*)&ua.y;
    __half2 b0 = *(__half2*)&ub.x, b1 = *(__half2*)&ub.y;
    float2 fa0 = __half22float2(a0), fa1 = __half22float2(a1);
    float2 fb0 = __half22float2(b0), fb1 = __half22float2(b1);

    float mx = fmaxf(fmaxf(fmaxf(fa0.x, fa0.y), fmaxf(fa1.x, fa1.y)),
                     fmaxf(fmaxf(fb0.x, fb0.y), fmaxf(fb1.x, fb1.y)));

    __shared__ float red[256];
    red[tid] = mx; __syncthreads();
    for (int off = 128; off > 0; off >>= 1) {
        if (tid < off) red[tid] = fmaxf(red[tid], red[tid + off]);
        __syncthreads();
    }
    mx = red[0]; __syncthreads();

    fa0.x = __expf(fa0.x - mx); fa0.y = __expf(fa0.y - mx);
    fa1.x = __expf(fa1.x - mx); fa1.y = __expf(fa1.y - mx);
    fb0.x = __expf(fb0.x - mx); fb0.y = __expf(fb0.y - mx);
    fb1.x = __expf(fb1.x - mx); fb1.y = __expf(fb1.y - mx);
    float s = (fa0.x + fa0.y + fa1.x + fa1.y) + (fb0.x + fb0.y + fb1.x + fb1.y);

    red[tid] = s; __syncthreads();
    for (int off = 128; off > 0; off >>= 1) {
        if (tid < off) red[tid] += red[tid + off];
        __syncthreads();
    }
    float rinv = 1.f / red[0];

    __half2 oa0 = __floats2half2_rn(fa0.x * rinv, fa0.y * rinv);
    __half2 oa1 = __floats2half2_rn(fa1.x * rinv, fa1.y * rinv);
    __half2 ob0 = __floats2half2_rn(fb0.x * rinv, fb0.y * rinv);
    __half2 ob1 = __floats2half2_rn(fb1.x * rinv, fb1.y * rinv);
    p4[tid]       = make_uint2(*(uint32_t*)&oa0, *(uint32_t*)&oa1);
    p4[tid + 256] = make_uint2(*(uint32_t*)&ob0, *(uint32_t*)&ob1);
}

// ---------------- launch ----------------
extern "C" void kernel_launch(void* const* d_in, const int* in_sizes, int n_in,
                              void* d_out, int out_size) {
    const float* x  = (const float*)d_in[0];
    const float* gs = (const float*)d_in[1];
    const float* gb = (const float*)d_in[2];
    const float* wq = (const float*)d_in[3];
    const float* bq = (const float*)d_in[4];
    const float* wk = (const float*)d_in[5];
    const float* bk = (const float*)d_in[6];
    const float* wv = (const float*)d_in[7];
    const float* bv = (const float*)d_in[8];
    const float* wp = (const float*)d_in[9];
    const float* bp = (const float*)d_in[10];
    float* out = (float*)d_out;

    cudaFuncSetAttribute(gemm_kernel<MODE_QKV, 8>,    cudaFuncAttributeMaxDynamicSharedMemorySize, GSMEM);
    cudaFuncSetAttribute(gemm_kernel<MODE_SCALE, 8>,  cudaFuncAttributeMaxDynamicSharedMemorySize, GSMEM);
    cudaFuncSetAttribute(gemm_kernel<MODE_NONE, 32>,  cudaFuncAttributeMaxDynamicSharedMemorySize, GSMEM);
    cudaFuncSetAttribute(gemm_kernel<MODE_OUT, 8>,    cudaFuncAttributeMaxDynamicSharedMemorySize, GSMEM);

    __half* hTh  = nullptr; cudaGetSymbolAddress((void**)&hTh,  g_hTh);
    __half* qTh  = nullptr; cudaGetSymbolAddress((void**)&qTh,  g_qTh);
    __half* kTh  = nullptr; cudaGetSymbolAddress((void**)&kTh,  g_kTh);
    __half* vh   = nullptr; cudaGetSymbolAddress((void**)&vh,   g_vh);
    __half* ph   = nullptr; cudaGetSymbolAddress((void**)&ph,   g_ph);
    __half* h2Th = nullptr; cudaGetSymbolAddress((void**)&h2Th, g_h2Th);
    __half* wh   = nullptr; cudaGetSymbolAddress((void**)&wh,   g_wh);
    __half* wqh = wh;
    __half* wkh = wh + (size_t)C_ * C_;
    __half* wvh = wh + 2 * (size_t)C_ * C_;
    __half* wph = wh + 3 * (size_t)C_ * C_;

    cvt_w_kernel<<<dim3(C_ * C_ / 1024, 4), 256>>>(wq, wk, wv, wp);
    groupnorm_kernel<<<B_ * GROUPS_, 256>>>(x, gs, gb);

    // merged QKV: 1536 blocks. seg0: qT = hT*wq^T + bq (col); seg1: kT; seg2: v = wv*hT^T + bv (row)
    gemm_kernel<MODE_QKV, 8><<<1536, 256, GSMEM>>>(
        hTh, wqh, qTh, bq, nullptr, wkh, bk, kTh, wvh, bv, vh,
        C_, C_, C_, NC_, 0, NC_, 0);

    // logits[i][j] = scale * sum_c qT[i][c] kT[j][c]  M=2048 N=2048 K=512 -> half
    gemm_kernel<MODE_SCALE, 8><<<dim3(16, 16, B_), 256, GSMEM>>>(
        qTh, kTh, ph, nullptr, nullptr, nullptr, nullptr, nullptr, nullptr, nullptr, nullptr,
        C_, C_, N_, NC_, NC_, NN_, 0);

    softmax_kernel<<<B_ * N_, 256>>>();

    // h2T[i][c] = sum_j P[i][j] v[c][j]               M=2048 N=512 K=2048
    gemm_kernel<MODE_NONE, 32><<<dim3(4, 16, B_), 256, GSMEM>>>(
        ph, vh, h2Th, nullptr, nullptr, nullptr, nullptr, nullptr, nullptr, nullptr, nullptr,
        N_, N_, C_, NN_, NC_, NC_, 0);

    // out[o][n] = x + bp[o] + sum_c wp[o][c] h2T[n][c]  M=512 N=2048 K=512
    gemm_kernel<MODE_OUT, 8><<<dim3(16, 4, B_), 256, GSMEM>>>(
        wph, h2Th, out, bp, x, nullptr, nullptr, nullptr, nullptr, nullptr, nullptr,
        C_, C_, N_, 0, NC_, NC_, NC_);
}

// round 16
// speedup vs baseline: 1.2459x; 1.0146x over previous
#include <cuda_runtime.h>
#include <cuda_fp16.h>
#include <cstdint>
#include <math.h>

#define B_   8
#define C_   512
#define N_   2048
#define GROUPS_ 32
#define CPG  16
#define EPSF 1e-6f

#define NC_ ((size_t)N_ * C_)      // 1048576
#define NN_ ((size_t)N_ * N_)      // 4194304

// ---------------- scratch ----------------
__device__ __half g_hTh [B_ * N_ * C_];          // groupnorm out, [b][n][c] half
__device__ __half g_qTh [B_ * N_ * C_];          // [b][n][c]  (pre-scaled by 1/sqrt(C))
__device__ __half g_kTh [B_ * N_ * C_];          // [b][n][c]
__device__ __half g_vh  [B_ * C_ * N_];          // [b][c][n]
__device__ __half g_ph  [(size_t)B_ * N_ * N_];  // logits -> probs, half, in-place
__device__ __half g_h2Th[B_ * N_ * C_];          // [b][i][c]
__device__ __half g_wh  [4 * C_ * C_];           // wq,wk,wv,wp as half

// ---------------- helpers ----------------
#define GDC_WAIT() asm volatile("griddepcontrol.wait;" ::: "memory")

__device__ __forceinline__ uint32_t smem_u32(const void* p) {
    uint32_t a;
    asm("{ .reg .u64 t; cvta.to.shared.u64 t, %1; cvt.u32.u64 %0, t; }" : "=r"(a) : "l"(p));
    return a;
}
__device__ __forceinline__ void cp_async16(uint32_t dst, const void* src) {
    asm volatile("cp.async.cg.shared.global [%0], [%1], 16;" :: "r"(dst), "l"(src));
}
#define CP_COMMIT() asm volatile("cp.async.commit_group;" ::: "memory")
#define CP_WAIT0()  asm volatile("cp.async.wait_group 0;" ::: "memory")

__device__ __forceinline__ void mma_f16(float* c, const uint32_t* a, const uint32_t* b) {
    asm volatile("mma.sync.aligned.m16n8k16.row.col.f32.f16.f16.f32 "
                 "{%0,%1,%2,%3}, {%4,%5,%6,%7}, {%8,%9}, {%0,%1,%2,%3};"
                 : "+f"(c[0]), "+f"(c[1]), "+f"(c[2]), "+f"(c[3])
                 : "r"(a[0]), "r"(a[1]), "r"(a[2]), "r"(a[3]), "r"(b[0]), "r"(b[1]));
}
__device__ __forceinline__ void ldm_x4(uint32_t& r0, uint32_t& r1, uint32_t& r2, uint32_t& r3,
                                       uint32_t addr) {
    asm volatile("ldmatrix.sync.aligned.m8n8.x4.shared.b16 {%0,%1,%2,%3}, [%4];"
                 : "=r"(r0), "=r"(r1), "=r"(r2), "=r"(r3) : "r"(addr));
}

// ---------------- weight fp32 -> fp16 ----------------
__global__ __launch_bounds__(256) void cvt_w_kernel(const float* __restrict__ wq,
                                                    const float* __restrict__ wk,
                                                    const float* __restrict__ wv,
                                                    const float* __restrict__ wp) {
    const float* src = (blockIdx.y == 0) ? wq : (blockIdx.y == 1) ? wk
                       : (blockIdx.y == 2) ? wv : wp;
    __half* dst = g_wh + (size_t)blockIdx.y * C_ * C_;
    int i = (blockIdx.x * 256 + threadIdx.x) * 4;
    float4 v = *(const float4*)(src + i);
    __half2 h0 = __floats2half2_rn(v.x, v.y);
    __half2 h1 = __floats2half2_rn(v.z, v.w);
    *(uint2*)(dst + i) = make_uint2(*(uint32_t*)&h0, *(uint32_t*)&h1);
}

// ---------------- GroupNorm (writes transposed half hT[b][n][c]) ----------------
// Independent of cvt_w; runs concurrently under PDL. GDC_WAIT at END preserves
// transitive ordering (groupnorm complete => cvt_w complete) for the QKV kernel.
__global__ __launch_bounds__(256) void groupnorm_kernel(const float* __restrict__ x,
                                                        const float* __restrict__ scale,
                                                        const float* __restrict__ bias) {
    int bg = blockIdx.x;
    int b = bg / GROUPS_, g = bg % GROUPS_;
    const float* xp  = x + ((size_t)b * C_ + (size_t)g * CPG) * N_;
    __half*      hpT = g_hTh + (size_t)b * NC_;
    int tid = threadIdx.x;
    const int total = CPG * N_;  // 32768

    float s = 0.f, ss = 0.f;
    for (int i = tid; i < total; i += 256) {
        float v = xp[i];
        s += v; ss += v * v;
    }
    __shared__ float rs[256], rq[256];
    rs[tid] = s; rq[tid] = ss;
    __syncthreads();
    for (int off = 128; off > 0; off >>= 1) {
        if (tid < off) { rs[tid] += rs[tid + off]; rq[tid] += rq[tid + off]; }
        __syncthreads();
    }
    float mean = rs[0] / (float)total;
    float var  = rq[0] / (float)total - mean * mean;
    float rinv = rsqrtf(var + EPSF);

    __shared__ float tile[128][17];
    for (int n0 = 0; n0 < N_; n0 += 128) {
        __syncthreads();
        int nl = tid & 127;
        int ch = tid >> 7;
        #pragma unroll
        for (int cp = 0; cp < 8; cp++) {
            int c = cp * 2 + ch;
            int cabs = g * CPG + c;
            tile[nl][c] = (xp[(size_t)c * N_ + n0 + nl] - mean) * rinv * scale[cabs] + bias[cabs];
        }
        __syncthreads();
        int row = tid >> 1;
        int half = (tid & 1) * 8;
        __half* dst = hpT + (size_t)(n0 + row) * C_ + g * CPG + half;
        __half2 h0 = __floats2half2_rn(tile[row][half + 0], tile[row][half + 1]);
        __half2 h1 = __floats2half2_rn(tile[row][half + 2], tile[row][half + 3]);
        __half2 h2 = __floats2half2_rn(tile[row][half + 4], tile[row][half + 5]);
        __half2 h3 = __floats2half2_rn(tile[row][half + 6], tile[row][half + 7]);
        *(uint4*)dst = make_uint4(*(uint32_t*)&h0, *(uint32_t*)&h1,
                                  *(uint32_t*)&h2, *(uint32_t*)&h3);
    }
    GDC_WAIT();   // order after cvt_w (transitive dependency for QKV)
}

// ---------------- fp16 mma.sync GEMM (champion mainloop) ----------------
// D[m][n] = sum_k A[m][k] * B[n][k], both K-major half.
#define MODE_NONE  3   // D half                     (QK logits / PV)
#define MODE_OUT   4   // + bias[row] + resid, float (proj)
#define MODE_QKV   5   // flat grid: seg0 colbias+scale q; seg1 colbias k; seg2 rowbias v

#define BKH    64
#define PADH   72
#define STAGEH (128 * PADH)
#define GSMEM  (3 * 2 * STAGEH * 2)   // 110592 bytes

template <int MODE, int NCK>
__global__ __launch_bounds__(256, 2)
void gemm_kernel(const __half* __restrict__ A, const __half* __restrict__ Bm,
                 void* __restrict__ Dv,
                 const float* __restrict__ bias, const float* __restrict__ resid,
                 const __half* __restrict__ Bm2, const float* __restrict__ bias2,
                 void* __restrict__ Dv2,
                 const __half* __restrict__ Bm3, const float* __restrict__ bias3,
                 void* __restrict__ Dv3,
                 int lda, int ldb, int ldd,
                 size_t a_bs, size_t b_bs, size_t d_bs, size_t r_bs) {
    extern __shared__ __half smem[];

    int tid = threadIdx.x, lane = tid & 31, wid = tid >> 5;
    int warp_m = wid & 3;     // 4 warps over M (32 rows)
    int warp_n = wid >> 2;    // 2 warps over N (64 cols)

    int b, m0, n0, seg = 0;
    const __half* Aptr = A;
    const __half* Bptr = Bm;
    const float*  bsel = bias;
    void*         Dsel = Dv;
    int lddv = ldd;
    if (MODE == MODE_QKV) {
        int id = blockIdx.x;
        seg = id >> 9;                  // 0:q 1:k 2:v
        int r = id & 511;
        int bx, by;
        if (seg < 2) { bx = r & 3;  by = (r >> 2) & 15; }
        else         { bx = r & 15; by = (r >> 4) & 3;  }
        b = r >> 6;                     // 64 tiles per batch in every segment
        m0 = by * 128; n0 = bx * 128;
        if (seg == 0) { /* defaults */ }
        else if (seg == 1) { Bptr = Bm2; bsel = bias2; Dsel = Dv2; }
        else { Aptr = Bm3; Bptr = A; bsel = bias3; Dsel = Dv3; lddv = N_; }
    } else {
        b = blockIdx.z;
        m0 = blockIdx.y * 128; n0 = blockIdx.x * 128;
    }

    const __half* Ab;
    const __half* Bb;
    if (MODE == MODE_QKV) {
        if (seg < 2) { Ab = Aptr + (size_t)b * NC_; Bb = Bptr; }
        else         { Ab = Aptr;                   Bb = Bptr + (size_t)b * NC_; }
    } else {
        Ab = Aptr + (size_t)b * a_bs;
        Bb = Bptr + (size_t)b * b_bs;
    }

    uint32_t sbase = smem_u32(smem);

    GDC_WAIT();   // predecessor grid complete before reading its output

    auto load_stage = [&](int stage, int k0) {
        uint32_t sa = sbase + (uint32_t)stage * (2u * STAGEH * 2u);
        uint32_t sb = sa + STAGEH * 2u;
        #pragma unroll
        for (int t = 0; t < 4; t++) {
            int idx = t * 256 + tid;
            int r = idx >> 3, c = idx & 7;
            uint32_t off = (uint32_t)(r * PADH + c * 8) * 2u;
            cp_async16(sa + off, Ab + (size_t)(m0 + r) * lda + k0 + c * 8);
            cp_async16(sb + off, Bb + (size_t)(n0 + r) * ldb + k0 + c * 8);
        }
    };

    int l7  = lane & 7;
    int l8  = (lane >> 3) & 1;
    int l16 = lane >> 4;
    int aoff = (warp_m * 32 + l7 + l8 * 8) * PADH + l16 * 8;
    int boff = (warp_n * 64 + l7 + l16 * 8) * PADH + l8 * 8;

    auto ldfragA = [&](uint32_t sa, int kbase, uint32_t fa[2][4]) {
        #pragma unroll
        for (int mt = 0; mt < 2; mt++) {
            uint32_t addr = sa + (uint32_t)(aoff + mt * 16 * PADH + kbase) * 2u;
            ldm_x4(fa[mt][0], fa[mt][1], fa[mt][2], fa[mt][3], addr);
        }
    };
    auto ldfragB = [&](uint32_t sb, int kbase, uint32_t fb[8][2]) {
        #pragma unroll
        for (int pp = 0; pp < 4; pp++) {
            uint32_t addr = sb + (uint32_t)(boff + pp * 16 * PADH + kbase) * 2u;
            ldm_x4(fb[2 * pp][0], fb[2 * pp][1], fb[2 * pp + 1][0], fb[2 * pp + 1][1], addr);
        }
    };

    float acc[2][8][4];
    #pragma unroll
    for (int i = 0; i < 2; i++)
        #pragma unroll
        for (int j = 0; j < 8; j++)
            #pragma unroll
            for (int t = 0; t < 4; t++) acc[i][j][t] = 0.f;

    uint32_t fA[2][2][4];   // double-buffered A fragments
    uint32_t fB[2][8][2];   // double-buffered B fragments

    load_stage(0, 0);
    CP_COMMIT();
    CP_WAIT0();
    __syncthreads();
    load_stage(1, BKH);
    CP_COMMIT();
    ldfragA(sbase, 0, fA[0]);
    ldfragB(sbase + STAGEH * 2u, 0, fB[0]);

    int stage = 0;
    #pragma unroll 1
    for (int ck = 0; ck < NCK; ck++) {
        CP_WAIT0();
        __syncthreads();

        int lst = stage + 2; if (lst >= 3) lst -= 3;
        if (ck + 2 < NCK) load_stage(lst, (ck + 2) * BKH);
        CP_COMMIT();

        uint32_t sa = sbase + (uint32_t)stage * (2u * STAGEH * 2u);
        uint32_t sb = sa + STAGEH * 2u;
        int nst = stage + 1; if (nst >= 3) nst -= 3;
        uint32_t xsa = sbase + (uint32_t)nst * (2u * STAGEH * 2u);
        uint32_t xsb = xsa + STAGEH * 2u;

        #pragma unroll
        for (int kk = 0; kk < 4; kk++) {
            int cur = kk & 1, nxt = cur ^ 1;
            if (kk < 3) {
                ldfragA(sa, (kk + 1) * 16, fA[nxt]);
                ldfragB(sb, (kk + 1) * 16, fB[nxt]);
            } else {      // cross-chunk prefetch (stage ck+1 already resident)
                ldfragA(xsa, 0, fA[nxt]);
                ldfragB(xsb, 0, fB[nxt]);
            }
            #pragma unroll
            for (int mt = 0; mt < 2; mt++)
                #pragma unroll
                for (int nt = 0; nt < 8; nt++)
                    mma_f16(acc[mt][nt], fA[cur][mt], fB[cur][nt]);
        }
        stage = nst;
    }

    // epilogue
    constexpr bool HALF_OUT = (MODE != MODE_OUT);
    int rbase = m0 + warp_m * 32 + (lane >> 2);
    int cbase = n0 + warp_n * 64 + (lane & 3) * 2;
    bool rowbias = (MODE == MODE_OUT) || (MODE == MODE_QKV && seg == 2);
    bool colbias = (MODE == MODE_QKV && seg < 2);
    bool qscale  = (MODE == MODE_QKV && seg == 0);
    const float scl = 0.044194173824159216f;   // 512^-0.5, folded into q
    #pragma unroll
    for (int mt = 0; mt < 2; mt++) {
        int r0 = rbase + mt * 16;
        int r1 = r0 + 8;
        float rb0 = 0.f, rb1 = 0.f;
        if (rowbias) { rb0 = bsel[r0]; rb1 = bsel[r1]; }
        #pragma unroll
        for (int nt = 0; nt < 8; nt++) {
            int cc = cbase + nt * 8;
            float e0 = acc[mt][nt][0], e1 = acc[mt][nt][1];
            float e2 = acc[mt][nt][2], e3 = acc[mt][nt][3];
            if (colbias) {
                float b0 = bsel[cc], b1 = bsel[cc + 1];
                e0 += b0; e1 += b1; e2 += b0; e3 += b1;
                if (qscale) { e0 *= scl; e1 *= scl; e2 *= scl; e3 *= scl; }
            } else if (rowbias) {
                e0 += rb0; e1 += rb0; e2 += rb1; e3 += rb1;
            }
            if (MODE == MODE_OUT) {
                const float* rp0 = resid + (size_t)b * r_bs + (size_t)r0 * lddv + cc;
                const float* rp1 = resid + (size_t)b * r_bs + (size_t)r1 * lddv + cc;
                e0 += rp0[0]; e1 += rp0[1];
                e2 += rp1[0]; e3 += rp1[1];
            }
            if (HALF_OUT) {
                __half* Dh = (__half*)Dsel + (size_t)b * ((MODE == MODE_QKV) ? NC_ : d_bs);
                __half2 h0 = __floats2half2_rn(e0, e1);
                __half2 h1 = __floats2half2_rn(e2, e3);
                *(__half2*)(Dh + (size_t)r0 * lddv + cc) = h0;
                *(__half2*)(Dh + (size_t)r1 * lddv + cc) = h1;
            } else {
                float* Df = (float*)Dsel + (size_t)b * d_bs;
                float2 o0; o0.x = e0; o0.y = e1;
                float2 o1; o1.x = e2; o1.y = e3;
                *(float2*)(Df + (size_t)r0 * lddv + cc) = o0;
                *(float2*)(Df + (size_t)r1 * lddv + cc) = o1;
            }
        }
    }
}

// ---------------- row softmax: half logits -> half probs (in place) ----------------
__global__ __launch_bounds__(256) void softmax_kernel() {
    size_t row = blockIdx.x;
    uint2* p4 = (uint2*)(g_ph + row * N_);
    int tid = threadIdx.x;

    GDC_WAIT();

    uint2 ua = p4[tid];
    uint2 ub = p4[tid + 256];
    __half2 a0 = *(__half2*)&ua.x, a1 = *(__half2*)&ua.y;
    __half2 b0 = *(__half2*)&ub.x, b1 = *(__half2*)&ub.y;
    float2 fa0 = __half22float2(a0), fa1 = __half22float2(a1);
    float2 fb0 = __half22float2(b0), fb1 = __half22float2(b1);

    float mx = fmaxf(fmaxf(fmaxf(fa0.x, fa0.y), fmaxf(fa1.x, fa1.y)),
                     fmaxf(fmaxf(fb0.x, fb0.y), fmaxf(fb1.x, fb1.y)));

    __shared__ float red[256];
    red[tid] = mx; __syncthreads();
    for (int off = 128; off > 0; off >>= 1) {
        if (tid < off) red[tid] = fmaxf(red[tid], red[tid + off]);
        __syncthreads();
    }
    mx = red[0]; __syncthreads();

    fa0.x = __expf(fa0.x - mx); fa0.y = __expf(fa0.y - mx);
    fa1.x = __expf(fa1.x - mx); fa1.y = __expf(fa1.y - mx);
    fb0.x = __expf(fb0.x - mx); fb0.y = __expf(fb0.y - mx);
    fb1.x = __expf(fb1.x - mx); fb1.y = __expf(fb1.y - mx);
    float s = (fa0.x + fa0.y + fa1.x + fa1.y) + (fb0.x + fb0.y + fb1.x + fb1.y);

    red[tid] = s; __syncthreads();
    for (int off = 128; off > 0; off >>= 1) {
        if (tid < off) red[tid] += red[tid + off];
        __syncthreads();
    }
    float rinv = 1.f / red[0];

    __half2 oa0 = __floats2half2_rn(fa0.x * rinv, fa0.y * rinv);
    __half2 oa1 = __floats2half2_rn(fa1.x * rinv, fa1.y * rinv);
    __half2 ob0 = __floats2half2_rn(fb0.x * rinv, fb0.y * rinv);
    __half2 ob1 = __floats2half2_rn(fb1.x * rinv, fb1.y * rinv);
    p4[tid]       = make_uint2(*(uint32_t*)&oa0, *(uint32_t*)&oa1);
    p4[tid + 256] = make_uint2(*(uint32_t*)&ob0, *(uint32_t*)&ob1);
}

// ---------------- launch ----------------
template <typename F, typename... Args>
static inline void launch_pdl(F f, dim3 g, dim3 b, size_t shmem, Args... args) {
    cudaLaunchConfig_t cfg = {};
    cfg.gridDim = g;
    cfg.blockDim = b;
    cfg.dynamicSmemBytes = shmem;
    cfg.stream = 0;
    cudaLaunchAttribute attr[1];
    attr[0].id = cudaLaunchAttributeProgrammaticStreamSerialization;
    attr[0].val.programmaticStreamSerializationAllowed = 1;
    cfg.attrs = attr;
    cfg.numAttrs = 1;
    cudaLaunchKernelEx(&cfg, f, args...);
}

extern "C" void kernel_launch(void* const* d_in, const int* in_sizes, int n_in,
                              void* d_out, int out_size) {
    const float* x  = (const float*)d_in[0];
    const float* gs = (const float*)d_in[1];
    const float* gb = (const float*)d_in[2];
    const float* wq = (const float*)d_in[3];
    const float* bq = (const float*)d_in[4];
    const float* wk = (const float*)d_in[5];
    const float* bk = (const float*)d_in[6];
    const float* wv = (const float*)d_in[7];
    const float* bv = (const float*)d_in[8];
    const float* wp = (const float*)d_in[9];
    const float* bp = (const float*)d_in[10];
    float* out = (float*)d_out;

    cudaFuncSetAttribute(gemm_kernel<MODE_QKV, 8>,   cudaFuncAttributeMaxDynamicSharedMemorySize, GSMEM);
    cudaFuncSetAttribute(gemm_kernel<MODE_NONE, 8>,  cudaFuncAttributeMaxDynamicSharedMemorySize, GSMEM);
    cudaFuncSetAttribute(gemm_kernel<MODE_NONE, 32>, cudaFuncAttributeMaxDynamicSharedMemorySize, GSMEM);
    cudaFuncSetAttribute(gemm_kernel<MODE_OUT, 8>,   cudaFuncAttributeMaxDynamicSharedMemorySize, GSMEM);

    __half* hTh  = nullptr; cudaGetSymbolAddress((void**)&hTh,  g_hTh);
    __half* qTh  = nullptr; cudaGetSymbolAddress((void**)&qTh,  g_qTh);
    __half* kTh  = nullptr; cudaGetSymbolAddress((void**)&kTh,  g_kTh);
    __half* vh   = nullptr; cudaGetSymbolAddress((void**)&vh,   g_vh);
    __half* ph   = nullptr; cudaGetSymbolAddress((void**)&ph,   g_ph);
    __half* h2Th = nullptr; cudaGetSymbolAddress((void**)&h2Th, g_h2Th);
    __half* wh   = nullptr; cudaGetSymbolAddress((void**)&wh,   g_wh);
    __half* wqh = wh;
    __half* wkh = wh + (size_t)C_ * C_;
    __half* wvh = wh + 2 * (size_t)C_ * C_;
    __half* wph = wh + 3 * (size_t)C_ * C_;

    cvt_w_kernel<<<dim3(C_ * C_ / 1024, 4), 256>>>(wq, wk, wv, wp);

    // groupnorm: PDL -> overlaps cvt_w fully (no data dependency); waits at its end
    launch_pdl(groupnorm_kernel, dim3(B_ * GROUPS_), dim3(256), 0, x, gs, gb);

    // merged QKV: seg0 q (colbias + scale-fold), seg1 k (colbias), seg2 v (rowbias)
    launch_pdl(gemm_kernel<MODE_QKV, 8>, dim3(1536), dim3(256), (size_t)GSMEM,
               (const __half*)hTh, (const __half*)wqh, (void*)qTh, bq, (const float*)nullptr,
               (const __half*)wkh, bk, (void*)kTh,
               (const __half*)wvh, bv, (void*)vh,
               C_, C_, C_, NC_, (size_t)0, NC_, (size_t)0);

    // logits[i][j] = sum_c q'[i][c] k[j][c]  (scale pre-folded into q')
    launch_pdl(gemm_kernel<MODE_NONE, 8>, dim3(16, 16, B_), dim3(256), (size_t)GSMEM,
               (const __half*)qTh, (const __half*)kTh, (void*)ph,
               (const float*)nullptr, (const float*)nullptr,
               (const __half*)nullptr, (const float*)nullptr, (void*)nullptr,
               (const __half*)nullptr, (const float*)nullptr, (void*)nullptr,
               C_, C_, N_, NC_, NC_, NN_, (size_t)0);

    launch_pdl(softmax_kernel, dim3(B_ * N_), dim3(256), 0);

    // h2T[i][c] = sum_j P[i][j] v[c][j]
    launch_pdl(gemm_kernel<MODE_NONE, 32>, dim3(4, 16, B_), dim3(256), (size_t)GSMEM,
               (const __half*)ph, (const __half*)vh, (void*)h2Th,
               (const float*)nullptr, (const float*)nullptr,
               (const __half*)nullptr, (const float*)nullptr, (void*)nullptr,
               (const __half*)nullptr, (const float*)nullptr, (void*)nullptr,
               N_, N_, C_, NN_, NC_, NC_, (size_t)0);

    // out[o][n] = x + bp[o] + sum_c wp[o][c] h2T[n][c]
    launch_pdl(gemm_kernel<MODE_OUT, 8>, dim3(16, 4, B_), dim3(256), (size_t)GSMEM,
               (const __half*)wph, (const __half*)h2Th, (void*)out,
               bp, x,
               (const __half*)nullptr, (const float*)nullptr, (void*)nullptr,
               (const __half*)nullptr, (const float*)nullptr, (void*)nullptr,
               C_, C_, N_, (size_t)0, NC_, NC_, NC_);
}

// round 17
// speedup vs baseline: 1.2521x; 1.0050x over previous
#include <cuda_runtime.h>
#include <cuda_fp16.h>
#include <cstdint>
#include <math.h>

#define B_   8
#define C_   512
#define N_   2048
#define GROUPS_ 32
#define CPG  16
#define EPSF 1e-6f

#define NC_ ((size_t)N_ * C_)      // 1048576
#define NN_ ((size_t)N_ * N_)      // 4194304

// ---------------- scratch ----------------
__device__ __half g_hTh [B_ * N_ * C_];          // groupnorm out, [b][n][c] half
__device__ __half g_qTh [B_ * N_ * C_];          // [b][n][c]  (pre-scaled by 1/sqrt(C))
__device__ __half g_kTh [B_ * N_ * C_];          // [b][n][c]
__device__ __half g_vh  [B_ * C_ * N_];          // [b][c][n]
__device__ __half g_ph  [(size_t)B_ * N_ * N_];  // logits -> probs, half, in-place
__device__ __half g_h2Th[B_ * N_ * C_];          // [b][i][c]
__device__ __half g_wh  [4 * C_ * C_];           // wq,wk,wv,wp as half

// ---------------- helpers ----------------
#define GDC_WAIT() asm volatile("griddepcontrol.wait;" ::: "memory")

__device__ __forceinline__ uint32_t smem_u32(const void* p) {
    uint32_t a;
    asm("{ .reg .u64 t; cvta.to.shared.u64 t, %1; cvt.u32.u64 %0, t; }" : "=r"(a) : "l"(p));
    return a;
}
__device__ __forceinline__ void cp_async16(uint32_t dst, const void* src) {
    asm volatile("cp.async.cg.shared.global [%0], [%1], 16;" :: "r"(dst), "l"(src));
}
#define CP_COMMIT() asm volatile("cp.async.commit_group;" ::: "memory")
#define CP_WAIT0()  asm volatile("cp.async.wait_group 0;" ::: "memory")

__device__ __forceinline__ void mma_f16(float* c, const uint32_t* a, const uint32_t* b) {
    asm volatile("mma.sync.aligned.m16n8k16.row.col.f32.f16.f16.f32 "
                 "{%0,%1,%2,%3}, {%4,%5,%6,%7}, {%8,%9}, {%0,%1,%2,%3};"
                 : "+f"(c[0]), "+f"(c[1]), "+f"(c[2]), "+f"(c[3])
                 : "r"(a[0]), "r"(a[1]), "r"(a[2]), "r"(a[3]), "r"(b[0]), "r"(b[1]));
}
__device__ __forceinline__ void ldm_x4(uint32_t& r0, uint32_t& r1, uint32_t& r2, uint32_t& r3,
                                       uint32_t addr) {
    asm volatile("ldmatrix.sync.aligned.m8n8.x4.shared.b16 {%0,%1,%2,%3}, [%4];"
                 : "=r"(r0), "=r"(r1), "=r"(r2), "=r"(r3) : "r"(addr));
}

// ---------------- weight fp32 -> fp16 ----------------
__global__ __launch_bounds__(256) void cvt_w_kernel(const float* __restrict__ wq,
                                                    const float* __restrict__ wk,
                                                    const float* __restrict__ wv,
                                                    const float* __restrict__ wp) {
    const float* src = (blockIdx.y == 0) ? wq : (blockIdx.y == 1) ? wk
                       : (blockIdx.y == 2) ? wv : wp;
    __half* dst = g_wh + (size_t)blockIdx.y * C_ * C_;
    int i = (blockIdx.x * 256 + threadIdx.x) * 4;
    float4 v = *(const float4*)(src + i);
    __half2 h0 = __floats2half2_rn(v.x, v.y);
    __half2 h1 = __floats2half2_rn(v.z, v.w);
    *(uint2*)(dst + i) = make_uint2(*(uint32_t*)&h0, *(uint32_t*)&h1);
}

// ---------------- GroupNorm: single gmem read, x cached in dynamic smem ----------------
// Independent of cvt_w; GDC_WAIT at END keeps transitive ordering for QKV.
#define GN_SMEM (CPG * N_ * 4)   // 131072 bytes: fp32 cache of the group slab

__global__ __launch_bounds__(256) void groupnorm_kernel(const float* __restrict__ x,
                                                        const float* __restrict__ scale,
                                                        const float* __restrict__ bias) {
    extern __shared__ float xs[];   // [CPG][N_]
    int bg = blockIdx.x;
    int b = bg / GROUPS_, g = bg % GROUPS_;
    const float* xp  = x + ((size_t)b * C_ + (size_t)g * CPG) * N_;
    __half*      hpT = g_hTh + (size_t)b * NC_;
    int tid = threadIdx.x;
    const int total = CPG * N_;  // 32768

    float s = 0.f, ss = 0.f;
    for (int i = tid; i < total; i += 256) {
        float v = xp[i];
        xs[i] = v;
        s += v; ss += v * v;
    }
    __shared__ float rs[256], rq[256];
    rs[tid] = s; rq[tid] = ss;
    __syncthreads();
    for (int off = 128; off > 0; off >>= 1) {
        if (tid < off) { rs[tid] += rs[tid + off]; rq[tid] += rq[tid + off]; }
        __syncthreads();
    }
    float mean = rs[0] / (float)total;
    float var  = rq[0] / (float)total - mean * mean;
    float rinv = rsqrtf(var + EPSF);

    __shared__ float tile[128][17];
    for (int n0 = 0; n0 < N_; n0 += 128) {
        __syncthreads();
        int nl = tid & 127;
        int ch = tid >> 7;
        #pragma unroll
        for (int cp = 0; cp < 8; cp++) {
            int c = cp * 2 + ch;
            int cabs = g * CPG + c;
            tile[nl][c] = (xs[c * N_ + n0 + nl] - mean) * rinv * scale[cabs] + bias[cabs];
        }
        __syncthreads();
        int row = tid >> 1;
        int half = (tid & 1) * 8;
        __half* dst = hpT + (size_t)(n0 + row) * C_ + g * CPG + half;
        __half2 h0 = __floats2half2_rn(tile[row][half + 0], tile[row][half + 1]);
        __half2 h1 = __floats2half2_rn(tile[row][half + 2], tile[row][half + 3]);
        __half2 h2 = __floats2half2_rn(tile[row][half + 4], tile[row][half + 5]);
        __half2 h3 = __floats2half2_rn(tile[row][half + 6], tile[row][half + 7]);
        *(uint4*)dst = make_uint4(*(uint32_t*)&h0, *(uint32_t*)&h1,
                                  *(uint32_t*)&h2, *(uint32_t*)&h3);
    }
    GDC_WAIT();   // order after cvt_w (transitive dependency for QKV)
}

// ---------------- fp16 mma.sync GEMM (champion mainloop) ----------------
// D[m][n] = sum_k A[m][k] * B[n][k], both K-major half.
#define MODE_NONE  3   // D half                     (QK logits / PV)
#define MODE_OUT   4   // + bias[row] + resid, float (proj)
#define MODE_QKV   5   // flat grid: seg0 colbias+scale q; seg1 colbias k; seg2 rowbias v

#define BKH    64
#define PADH   72
#define STAGEH (128 * PADH)
#define GSMEM  (3 * 2 * STAGEH * 2)   // 110592 bytes

template <int MODE, int NCK>
__global__ __launch_bounds__(256, 2)
void gemm_kernel(const __half* __restrict__ A, const __half* __restrict__ Bm,
                 void* __restrict__ Dv,
                 const float* __restrict__ bias, const float* __restrict__ resid,
                 const __half* __restrict__ Bm2, const float* __restrict__ bias2,
                 void* __restrict__ Dv2,
                 const __half* __restrict__ Bm3, const float* __restrict__ bias3,
                 void* __restrict__ Dv3,
                 int lda, int ldb, int ldd,
                 size_t a_bs, size_t b_bs, size_t d_bs, size_t r_bs) {
    extern __shared__ __half smem[];

    int tid = threadIdx.x, lane = tid & 31, wid = tid >> 5;
    int warp_m = wid & 3;     // 4 warps over M (32 rows)
    int warp_n = wid >> 2;    // 2 warps over N (64 cols)

    int b, m0, n0, seg = 0;
    const __half* Aptr = A;
    const __half* Bptr = Bm;
    const float*  bsel = bias;
    void*         Dsel = Dv;
    int lddv = ldd;
    if (MODE == MODE_QKV) {
        int id = blockIdx.x;
        seg = id >> 9;                  // 0:q 1:k 2:v
        int r = id & 511;
        int bx, by;
        if (seg < 2) { bx = r & 3;  by = (r >> 2) & 15; }
        else         { bx = r & 15; by = (r >> 4) & 3;  }
        b = r >> 6;                     // 64 tiles per batch in every segment
        m0 = by * 128; n0 = bx * 128;
        if (seg == 0) { /* defaults */ }
        else if (seg == 1) { Bptr = Bm2; bsel = bias2; Dsel = Dv2; }
        else { Aptr = Bm3; Bptr = A; bsel = bias3; Dsel = Dv3; lddv = N_; }
    } else {
        b = blockIdx.z;
        m0 = blockIdx.y * 128; n0 = blockIdx.x * 128;
    }

    const __half* Ab;
    const __half* Bb;
    if (MODE == MODE_QKV) {
        if (seg < 2) { Ab = Aptr + (size_t)b * NC_; Bb = Bptr; }
        else         { Ab = Aptr;                   Bb = Bptr + (size_t)b * NC_; }
    } else {
        Ab = Aptr + (size_t)b * a_bs;
        Bb = Bptr + (size_t)b * b_bs;
    }

    uint32_t sbase = smem_u32(smem);

    GDC_WAIT();   // predecessor grid complete before reading its output

    auto load_stage = [&](int stage, int k0) {
        uint32_t sa = sbase + (uint32_t)stage * (2u * STAGEH * 2u);
        uint32_t sb = sa + STAGEH * 2u;
        #pragma unroll
        for (int t = 0; t < 4; t++) {
            int idx = t * 256 + tid;
            int r = idx >> 3, c = idx & 7;
            uint32_t off = (uint32_t)(r * PADH + c * 8) * 2u;
            cp_async16(sa + off, Ab + (size_t)(m0 + r) * lda + k0 + c * 8);
            cp_async16(sb + off, Bb + (size_t)(n0 + r) * ldb + k0 + c * 8);
        }
    };

    int l7  = lane & 7;
    int l8  = (lane >> 3) & 1;
    int l16 = lane >> 4;
    int aoff = (warp_m * 32 + l7 + l8 * 8) * PADH + l16 * 8;
    int boff = (warp_n * 64 + l7 + l16 * 8) * PADH + l8 * 8;

    auto ldfragA = [&](uint32_t sa, int kbase, uint32_t fa[2][4]) {
        #pragma unroll
        for (int mt = 0; mt < 2; mt++) {
            uint32_t addr = sa + (uint32_t)(aoff + mt * 16 * PADH + kbase) * 2u;
            ldm_x4(fa[mt][0], fa[mt][1], fa[mt][2], fa[mt][3], addr);
        }
    };
    auto ldfragB = [&](uint32_t sb, int kbase, uint32_t fb[8][2]) {
        #pragma unroll
        for (int pp = 0; pp < 4; pp++) {
            uint32_t addr = sb + (uint32_t)(boff + pp * 16 * PADH + kbase) * 2u;
            ldm_x4(fb[2 * pp][0], fb[2 * pp][1], fb[2 * pp + 1][0], fb[2 * pp + 1][1], addr);
        }
    };

    float acc[2][8][4];
    #pragma unroll
    for (int i = 0; i < 2; i++)
        #pragma unroll
        for (int j = 0; j < 8; j++)
            #pragma unroll
            for (int t = 0; t < 4; t++) acc[i][j][t] = 0.f;

    uint32_t fA[2][2][4];   // double-buffered A fragments
    uint32_t fB[2][8][2];   // double-buffered B fragments

    load_stage(0, 0);
    CP_COMMIT();
    CP_WAIT0();
    __syncthreads();
    load_stage(1, BKH);
    CP_COMMIT();
    ldfragA(sbase, 0, fA[0]);
    ldfragB(sbase + STAGEH * 2u, 0, fB[0]);

    int stage = 0;
    #pragma unroll 1
    for (int ck = 0; ck < NCK; ck++) {
        CP_WAIT0();
        __syncthreads();

        int lst = stage + 2; if (lst >= 3) lst -= 3;
        if (ck + 2 < NCK) load_stage(lst, (ck + 2) * BKH);
        CP_COMMIT();

        uint32_t sa = sbase + (uint32_t)stage * (2u * STAGEH * 2u);
        uint32_t sb = sa + STAGEH * 2u;
        int nst = stage + 1; if (nst >= 3) nst -= 3;
        uint32_t xsa = sbase + (uint32_t)nst * (2u * STAGEH * 2u);
        uint32_t xsb = xsa + STAGEH * 2u;

        #pragma unroll
        for (int kk = 0; kk < 4; kk++) {
            int cur = kk & 1, nxt = cur ^ 1;
            if (kk < 3) {
                ldfragA(sa, (kk + 1) * 16, fA[nxt]);
                ldfragB(sb, (kk + 1) * 16, fB[nxt]);
            } else {      // cross-chunk prefetch (stage ck+1 already resident)
                ldfragA(xsa, 0, fA[nxt]);
                ldfragB(xsb, 0, fB[nxt]);
            }
            #pragma unroll
            for (int mt = 0; mt < 2; mt++)
                #pragma unroll
                for (int nt = 0; nt < 8; nt++)
                    mma_f16(acc[mt][nt], fA[cur][mt], fB[cur][nt]);
        }
        stage = nst;
    }

    // epilogue
    constexpr bool HALF_OUT = (MODE != MODE_OUT);
    int rbase = m0 + warp_m * 32 + (lane >> 2);
    int cbase = n0 + warp_n * 64 + (lane & 3) * 2;
    bool rowbias = (MODE == MODE_OUT) || (MODE == MODE_QKV && seg == 2);
    bool colbias = (MODE == MODE_QKV && seg < 2);
    bool qscale  = (MODE == MODE_QKV && seg == 0);
    const float scl = 0.044194173824159216f;   // 512^-0.5, folded into q
    #pragma unroll
    for (int mt = 0; mt < 2; mt++) {
        int r0 = rbase + mt * 16;
        int r1 = r0 + 8;
        float rb0 = 0.f, rb1 = 0.f;
        if (rowbias) { rb0 = bsel[r0]; rb1 = bsel[r1]; }
        #pragma unroll
        for (int nt = 0; nt < 8; nt++) {
            int cc = cbase + nt * 8;
            float e0 = acc[mt][nt][0], e1 = acc[mt][nt][1];
            float e2 = acc[mt][nt][2], e3 = acc[mt][nt][3];
            if (colbias) {
                float b0 = bsel[cc], b1 = bsel[cc + 1];
                e0 += b0; e1 += b1; e2 += b0; e3 += b1;
                if (qscale) { e0 *= scl; e1 *= scl; e2 *= scl; e3 *= scl; }
            } else if (rowbias) {
                e0 += rb0; e1 += rb0; e2 += rb1; e3 += rb1;
            }
            if (MODE == MODE_OUT) {
                const float* rp0 = resid + (size_t)b * r_bs + (size_t)r0 * lddv + cc;
                const float* rp1 = resid + (size_t)b * r_bs + (size_t)r1 * lddv + cc;
                e0 += rp0[0]; e1 += rp0[1];
                e2 += rp1[0]; e3 += rp1[1];
            }
            if (HALF_OUT) {
                __half* Dh = (__half*)Dsel + (size_t)b * ((MODE == MODE_QKV) ? NC_ : d_bs);
                __half2 h0 = __floats2half2_rn(e0, e1);
                __half2 h1 = __floats2half2_rn(e2, e3);
                *(__half2*)(Dh + (size_t)r0 * lddv + cc) = h0;
                *(__half2*)(Dh + (size_t)r1 * lddv + cc) = h1;
            } else {
                float* Df = (float*)Dsel + (size_t)b * d_bs;
                float2 o0; o0.x = e0; o0.y = e1;
                float2 o1; o1.x = e2; o1.y = e3;
                *(float2*)(Df + (size_t)r0 * lddv + cc) = o0;
                *(float2*)(Df + (size_t)r1 * lddv + cc) = o1;
            }
        }
    }
}

// ---------------- row softmax: warp-per-row, shuffle reductions, in place ----------------
// 8 warps per block, each warp owns one row of 2048 halves (64 per lane).
__global__ __launch_bounds__(256) void softmax_kernel() {
    int wid = threadIdx.x >> 5, lane = threadIdx.x & 31;
    size_t row = (size_t)blockIdx.x * 8 + wid;
    uint2* p4 = (uint2*)(g_ph + row * N_);      // 512 uint2 per row

    GDC_WAIT();

    float v[64];
    float mx = -1e30f;
    #pragma unroll
    for (int i = 0; i < 16; i++) {
        uint2 u = p4[lane + 32 * i];
        __half2 h0 = *(__half2*)&u.x, h1 = *(__half2*)&u.y;
        float2 f0 = __half22float2(h0), f1 = __half22float2(h1);
        v[4 * i + 0] = f0.x; v[4 * i + 1] = f0.y;
        v[4 * i + 2] = f1.x; v[4 * i + 3] = f1.y;
        mx = fmaxf(mx, fmaxf(fmaxf(f0.x, f0.y), fmaxf(f1.x, f1.y)));
    }
    #pragma unroll
    for (int o = 16; o; o >>= 1) mx = fmaxf(mx, __shfl_xor_sync(0xFFFFFFFFu, mx, o));

    float s = 0.f;
    #pragma unroll
    for (int i = 0; i < 64; i++) { v[i] = __expf(v[i] - mx); s += v[i]; }
    #pragma unroll
    for (int o = 16; o; o >>= 1) s += __shfl_xor_sync(0xFFFFFFFFu, s, o);
    float rinv = 1.f / s;

    #pragma unroll
    for (int i = 0; i < 16; i++) {
        __half2 h0 = __floats2half2_rn(v[4 * i + 0] * rinv, v[4 * i + 1] * rinv);
        __half2 h1 = __floats2half2_rn(v[4 * i + 2] * rinv, v[4 * i + 3] * rinv);
        p4[lane + 32 * i] = make_uint2(*(uint32_t*)&h0, *(uint32_t*)&h1);
    }
}

// ---------------- launch ----------------
template <typename F, typename... Args>
static inline void launch_pdl(F f, dim3 g, dim3 b, size_t shmem, Args... args) {
    cudaLaunchConfig_t cfg = {};
    cfg.gridDim = g;
    cfg.blockDim = b;
    cfg.dynamicSmemBytes = shmem;
    cfg.stream = 0;
    cudaLaunchAttribute attr[1];
    attr[0].id = cudaLaunchAttributeProgrammaticStreamSerialization;
    attr[0].val.programmaticStreamSerializationAllowed = 1;
    cfg.attrs = attr;
    cfg.numAttrs = 1;
    cudaLaunchKernelEx(&cfg, f, args...);
}

extern "C" void kernel_launch(void* const* d_in, const int* in_sizes, int n_in,
                              void* d_out, int out_size) {
    const float* x  = (const float*)d_in[0];
    const float* gs = (const float*)d_in[1];
    const float* gb = (const float*)d_in[2];
    const float* wq = (const float*)d_in[3];
    const float* bq = (const float*)d_in[4];
    const float* wk = (const float*)d_in[5];
    const float* bk = (const float*)d_in[6];
    const float* wv = (const float*)d_in[7];
    const float* bv = (const float*)d_in[8];
    const float* wp = (const float*)d_in[9];
    const float* bp = (const float*)d_in[10];
    float* out = (float*)d_out;

    cudaFuncSetAttribute(gemm_kernel<MODE_QKV, 8>,   cudaFuncAttributeMaxDynamicSharedMemorySize, GSMEM);
    cudaFuncSetAttribute(gemm_kernel<MODE_NONE, 8>,  cudaFuncAttributeMaxDynamicSharedMemorySize, GSMEM);
    cudaFuncSetAttribute(gemm_kernel<MODE_NONE, 32>, cudaFuncAttributeMaxDynamicSharedMemorySize, GSMEM);
    cudaFuncSetAttribute(gemm_kernel<MODE_OUT, 8>,   cudaFuncAttributeMaxDynamicSharedMemorySize, GSMEM);
    cudaFuncSetAttribute(groupnorm_kernel,           cudaFuncAttributeMaxDynamicSharedMemorySize, GN_SMEM);

    __half* hTh  = nullptr; cudaGetSymbolAddress((void**)&hTh,  g_hTh);
    __half* qTh  = nullptr; cudaGetSymbolAddress((void**)&qTh,  g_qTh);
    __half* kTh  = nullptr; cudaGetSymbolAddress((void**)&kTh,  g_kTh);
    __half* vh   = nullptr; cudaGetSymbolAddress((void**)&vh,   g_vh);
    __half* ph   = nullptr; cudaGetSymbolAddress((void**)&ph,   g_ph);
    __half* h2Th = nullptr; cudaGetSymbolAddress((void**)&h2Th, g_h2Th);
    __half* wh   = nullptr; cudaGetSymbolAddress((void**)&wh,   g_wh);
    __half* wqh = wh;
    __half* wkh = wh + (size_t)C_ * C_;
    __half* wvh = wh + 2 * (size_t)C_ * C_;
    __half* wph = wh + 3 * (size_t)C_ * C_;

    cvt_w_kernel<<<dim3(C_ * C_ / 1024, 4), 256>>>(wq, wk, wv, wp);

    // groupnorm: PDL -> overlaps cvt_w fully (no data dependency); waits at its end
    launch_pdl(groupnorm_kernel, dim3(B_ * GROUPS_), dim3(256), (size_t)GN_SMEM, x, gs, gb);

    // merged QKV: seg0 q (colbias + scale-fold), seg1 k (colbias), seg2 v (rowbias)
    launch_pdl(gemm_kernel<MODE_QKV, 8>, dim3(1536), dim3(256), (size_t)GSMEM,
               (const __half*)hTh, (const __half*)wqh, (void*)qTh, bq, (const float*)nullptr,
               (const __half*)wkh, bk, (void*)kTh,
               (const __half*)wvh, bv, (void*)vh,
               C_, C_, C_, NC_, (size_t)0, NC_, (size_t)0);

    // logits[i][j] = sum_c q'[i][c] k[j][c]  (scale pre-folded into q')
    launch_pdl(gemm_kernel<MODE_NONE, 8>, dim3(16, 16, B_), dim3(256), (size_t)GSMEM,
               (const __half*)qTh, (const __half*)kTh, (void*)ph,
               (const float*)nullptr, (const float*)nullptr,
               (const __half*)nullptr, (const float*)nullptr, (void*)nullptr,
               (const __half*)nullptr, (const float*)nullptr, (void*)nullptr,
               C_, C_, N_, NC_, NC_, NN_, (size_t)0);

    launch_pdl(softmax_kernel, dim3(B_ * N_ / 8), dim3(256), 0);

    // h2T[i][c] = sum_j P[i][j] v[c][j]
    launch_pdl(gemm_kernel<MODE_NONE, 32>, dim3(4, 16, B_), dim3(256), (size_t)GSMEM,
               (const __half*)ph, (const __half*)vh, (void*)h2Th,
               (const float*)nullptr, (const float*)nullptr,
               (const __half*)nullptr, (const float*)nullptr, (void*)nullptr,
               (const __half*)nullptr, (const float*)nullptr, (void*)nullptr,
               N_, N_, C_, NN_, NC_, NC_, (size_t)0);

    // out[o][n] = x + bp[o] + sum_c wp[o][c] h2T[n][c]
    launch_pdl(gemm_kernel<MODE_OUT, 8>, dim3(16, 4, B_), dim3(256), (size_t)GSMEM,
               (const __half*)wph, (const __half*)h2Th, (void*)out,
               bp, x,
               (const __half*)nullptr, (const float*)nullptr, (void*)nullptr,
               (const __half*)nullptr, (const float*)nullptr, (void*)nullptr,
               C_, C_, N_, (size_t)0, NC_, NC_, NC_);
}